// round 7
// baseline (speedup 1.0000x reference)
#include <cuda_runtime.h>
#include <math.h>
#include <stdint.h>

// Problem constants
#define S_IMG 2048
#define S_TXT 512
#define S_TOT 2560
#define DMODEL 1536
#define NHEAD 24
#define DHEAD 64

// Scratch (device globals; no allocation allowed)
__device__ __align__(16) float g_q[NHEAD * S_TOT * DHEAD];
__device__ __align__(16) float g_k[NHEAD * S_TOT * DHEAD];
__device__ __align__(16) float g_v[NHEAD * S_TOT * DHEAD];
__device__ __align__(16) float g_attn[S_TOT * DMODEL];

// ---------------------------------------------------------------------------
// tf32 helpers
// ---------------------------------------------------------------------------
__device__ __forceinline__ uint32_t f2tf(float x) {
    uint32_t u;
    asm("cvt.rna.tf32.f32 %0, %1;" : "=r"(u) : "f"(x));
    return u;
}

#define MMA_TF32(d, a, b)                                                     \
    asm volatile(                                                             \
        "mma.sync.aligned.m16n8k8.row.col.f32.tf32.tf32.f32 "                 \
        "{%0,%1,%2,%3}, {%4,%5,%6,%7}, {%8,%9}, {%0,%1,%2,%3};"               \
        : "+f"((d)[0]), "+f"((d)[1]), "+f"((d)[2]), "+f"((d)[3])              \
        : "r"((a)[0]), "r"((a)[1]), "r"((a)[2]), "r"((a)[3]),                 \
          "r"((b)[0]), "r"((b)[1]))

// ---------------------------------------------------------------------------
// Tensor-core GEMM (tf32): out = A[M,1536] @ W[1536,1536]^T + bias
//   gridDim.z selects (W, bias, out) triple -> batches QKV in one launch.
//   headmajor==1: out[(h*S_TOT + tok_off + m)*64 + d]  (n = h*64+d)
//   headmajor==0: out[m*1536 + n]
// Tiles: BM=BN=128, BK=32. 512 threads = 16 warps (4x4), warp tile 32x32.
// Smem [row][k] padded to stride 36 words -> all fragment LDS conflict-free.
// Double-buffered (global -> regs -> smem). Dynamic smem = 73728 B.
// ---------------------------------------------------------------------------
#define KPAD 36
#define TSZ (128 * KPAD)   // words per (matrix, buffer)

__global__ __launch_bounds__(512, 1)
void gemm_tc(const float* __restrict__ A,
             const float* __restrict__ W0, const float* __restrict__ W1,
             const float* __restrict__ W2,
             const float* __restrict__ bz0, const float* __restrict__ bz1,
             const float* __restrict__ bz2,
             float* __restrict__ o0, float* __restrict__ o1,
             float* __restrict__ o2,
             int headmajor, int tok_off)
{
    extern __shared__ uint32_t smu[];
    uint32_t* As = smu;              // [2][128][36]
    uint32_t* Bs = smu + 2 * TSZ;    // [2][128][36]

    const float* W    = (blockIdx.z == 0) ? W0  : (blockIdx.z == 1 ? W1  : W2);
    const float* bias = (blockIdx.z == 0) ? bz0 : (blockIdx.z == 1 ? bz1 : bz2);
    float* out        = (blockIdx.z == 0) ? o0  : (blockIdx.z == 1 ? o1  : o2);

    const int m0 = blockIdx.y * 128;
    const int n0 = blockIdx.x * 128;
    const int tid = threadIdx.x;
    const int lane = tid & 31;
    const int wid = tid >> 5;
    const int wm = wid >> 2;     // 0..3
    const int wn = wid & 3;      // 0..3
    const int gid = lane >> 2;   // 0..7
    const int tg = lane & 3;     // 0..3

    const float* Ap = A + (size_t)m0 * DMODEL;
    const float* Wp = W + (size_t)n0 * DMODEL;

    // Global-load coords: 2 float4 per matrix per thread.
    // f = tid + i*512; row = f>>3 (0..127); c4 = f&7 (float4 within 32-wide k)
    const int r0 = tid >> 3,          c0 = tid & 7;
    const int r1 = (tid + 512) >> 3,  c1 = (tid + 512) & 7;

    float acc[2][4][4];
#pragma unroll
    for (int mf = 0; mf < 2; mf++)
#pragma unroll
        for (int nf = 0; nf < 4; nf++)
#pragma unroll
            for (int j = 0; j < 4; j++) acc[mf][nf][j] = 0.0f;

    // Prologue: tile k0=0 -> buffer 0
    {
        float4 a0 = *(const float4*)(Ap + (size_t)r0 * DMODEL + c0 * 4);
        float4 a1 = *(const float4*)(Ap + (size_t)r1 * DMODEL + c1 * 4);
        float4 b0 = *(const float4*)(Wp + (size_t)r0 * DMODEL + c0 * 4);
        float4 b1 = *(const float4*)(Wp + (size_t)r1 * DMODEL + c1 * 4);
        uint32_t* d;
        d = As + r0 * KPAD + c0 * 4;
        d[0] = f2tf(a0.x); d[1] = f2tf(a0.y); d[2] = f2tf(a0.z); d[3] = f2tf(a0.w);
        d = As + r1 * KPAD + c1 * 4;
        d[0] = f2tf(a1.x); d[1] = f2tf(a1.y); d[2] = f2tf(a1.z); d[3] = f2tf(a1.w);
        d = Bs + r0 * KPAD + c0 * 4;
        d[0] = f2tf(b0.x); d[1] = f2tf(b0.y); d[2] = f2tf(b0.z); d[3] = f2tf(b0.w);
        d = Bs + r1 * KPAD + c1 * 4;
        d[0] = f2tf(b1.x); d[1] = f2tf(b1.y); d[2] = f2tf(b1.z); d[3] = f2tf(b1.w);
    }
    __syncthreads();

    int buf = 0;
    for (int k0 = 0; k0 < DMODEL; k0 += 32) {
        // Prefetch next tile into registers
        float4 pa0, pa1, pb0, pb1;
        const int kn = k0 + 32;
        if (kn < DMODEL) {
            pa0 = *(const float4*)(Ap + (size_t)r0 * DMODEL + kn + c0 * 4);
            pa1 = *(const float4*)(Ap + (size_t)r1 * DMODEL + kn + c1 * 4);
            pb0 = *(const float4*)(Wp + (size_t)r0 * DMODEL + kn + c0 * 4);
            pb1 = *(const float4*)(Wp + (size_t)r1 * DMODEL + kn + c1 * 4);
        }

        const uint32_t* asb = As + buf * TSZ;
        const uint32_t* bsb = Bs + buf * TSZ;

#pragma unroll
        for (int kk = 0; kk < 4; kk++) {
            const uint32_t* ak = asb + kk * 8;
            const uint32_t* bk = bsb + kk * 8;
            uint32_t a[2][4], b[4][2];
            const int ra = wm * 32 + gid;
            a[0][0] = ak[(ra)      * KPAD + tg];
            a[0][1] = ak[(ra + 8)  * KPAD + tg];
            a[0][2] = ak[(ra)      * KPAD + tg + 4];
            a[0][3] = ak[(ra + 8)  * KPAD + tg + 4];
            a[1][0] = ak[(ra + 16) * KPAD + tg];
            a[1][1] = ak[(ra + 24) * KPAD + tg];
            a[1][2] = ak[(ra + 16) * KPAD + tg + 4];
            a[1][3] = ak[(ra + 24) * KPAD + tg + 4];
#pragma unroll
            for (int nf = 0; nf < 4; nf++) {
                const int cb = wn * 32 + nf * 8 + gid;
                b[nf][0] = bk[cb * KPAD + tg];
                b[nf][1] = bk[cb * KPAD + tg + 4];
            }
#pragma unroll
            for (int mf = 0; mf < 2; mf++)
#pragma unroll
                for (int nf = 0; nf < 4; nf++)
                    MMA_TF32(acc[mf][nf], a[mf], b[nf]);
        }

        if (kn < DMODEL) {
            const int nb = buf ^ 1;
            uint32_t* d;
            d = As + nb * TSZ + r0 * KPAD + c0 * 4;
            d[0] = f2tf(pa0.x); d[1] = f2tf(pa0.y); d[2] = f2tf(pa0.z); d[3] = f2tf(pa0.w);
            d = As + nb * TSZ + r1 * KPAD + c1 * 4;
            d[0] = f2tf(pa1.x); d[1] = f2tf(pa1.y); d[2] = f2tf(pa1.z); d[3] = f2tf(pa1.w);
            d = Bs + nb * TSZ + r0 * KPAD + c0 * 4;
            d[0] = f2tf(pb0.x); d[1] = f2tf(pb0.y); d[2] = f2tf(pb0.z); d[3] = f2tf(pb0.w);
            d = Bs + nb * TSZ + r1 * KPAD + c1 * 4;
            d[0] = f2tf(pb1.x); d[1] = f2tf(pb1.y); d[2] = f2tf(pb1.z); d[3] = f2tf(pb1.w);
            __syncthreads();
            buf = nb;
        }
    }

    // Epilogue: c0/c1 -> row gid, cols tg*2, tg*2+1; c2/c3 -> row gid+8
#pragma unroll
    for (int mf = 0; mf < 2; mf++) {
        const int rowa = m0 + wm * 32 + mf * 16 + gid;
#pragma unroll
        for (int nf = 0; nf < 4; nf++) {
            const int n = n0 + wn * 32 + nf * 8 + tg * 2;
            float2 bb = *(const float2*)(bias + n);
            float2 v0 = make_float2(acc[mf][nf][0] + bb.x, acc[mf][nf][1] + bb.y);
            float2 v1 = make_float2(acc[mf][nf][2] + bb.x, acc[mf][nf][3] + bb.y);
            if (headmajor) {
                const int hh = n >> 6;
                const int dd = n & 63;
                float* p0 = out + ((size_t)(hh * S_TOT + tok_off + rowa)) * DHEAD + dd;
                float* p1 = out + ((size_t)(hh * S_TOT + tok_off + rowa + 8)) * DHEAD + dd;
                *(float2*)p0 = v0;
                *(float2*)p1 = v1;
            } else {
                *(float2*)(out + (size_t)rowa * DMODEL + n) = v0;
                *(float2*)(out + (size_t)(rowa + 8) * DMODEL + n) = v1;
            }
        }
    }
}

// ---------------------------------------------------------------------------
// Fused per-(token, head) RMS norm + RoPE on g_q and g_k (v untouched).
// One warp per 64-element row; lane handles elements (2*lane, 2*lane+1).
// ---------------------------------------------------------------------------
__global__ void rmsrope_kernel(const float* __restrict__ cosb,
                               const float* __restrict__ sinb,
                               const float* __restrict__ gq,
                               const float* __restrict__ gk,
                               const float* __restrict__ gaq,
                               const float* __restrict__ gak)
{
    int wg = (blockIdx.x * blockDim.x + threadIdx.x) >> 5;   // global warp id
    int lane = threadIdx.x & 31;
    const int ROWS = NHEAD * S_TOT;
    if (wg >= 2 * ROWS) return;

    int which = (wg >= ROWS) ? 1 : 0;      // 0 = q, 1 = k
    int r = which ? (wg - ROWS) : wg;      // r = h*S_TOT + s
    int s = r % S_TOT;

    float* ptr = (which ? g_k : g_q) + (size_t)r * DHEAD;
    const float* g = which ? (s < S_TXT ? gak : gk)
                           : (s < S_TXT ? gaq : gq);

    float2 x = ((float2*)ptr)[lane];
    float ss = x.x * x.x + x.y * x.y;
#pragma unroll
    for (int m = 16; m; m >>= 1) ss += __shfl_xor_sync(0xffffffffu, ss, m);
    float sc = rsqrtf(ss * (1.0f / DHEAD) + 1e-6f);

    float x0 = x.x * sc * g[2 * lane];
    float x1 = x.y * sc * g[2 * lane + 1];

    float c  = cosb[s * DHEAD + 2 * lane];   // repeated pairs: [2d] == [2d+1]
    float sn = sinb[s * DHEAD + 2 * lane];

    float2 y;
    y.x = x0 * c - x1 * sn;
    y.y = x1 * c + x0 * sn;
    ((float2*)ptr)[lane] = y;
}

// ---------------------------------------------------------------------------
// FlashAttention fp32. Grid: (S_TOT/64 q-tiles, NHEAD). 256 threads.
// 64x64 S tile; thread (ty,tx) in 16x16 grid owns 4x4 micro-tile.
// Qt/Kt transposed [d][row] with stride 68 (conflict-light); Vs/Ps natural.
// Dynamic smem: 4 * 64*68 * 4B = 69632 B.
// ---------------------------------------------------------------------------
#define SMSTR 68
__global__ __launch_bounds__(256, 2)
void attn_kernel()
{
    extern __shared__ float sm[];
    float* Qt = sm;                 // [64][68]  Qt[d][r]
    float* Kt = sm + 64 * SMSTR;    // [64][68]  Kt[d][c]
    float* Vs = sm + 2 * 64 * SMSTR;// [64][68]  Vs[c][dv]
    float* Ps = sm + 3 * 64 * SMSTR;// [64][68]  Ps[r][c]

    const int h = blockIdx.y;
    const int q0 = blockIdx.x * 64;
    const int tid = threadIdx.x;
    const int tx = tid & 15;
    const int ty = tid >> 4;

    const float* Qg = g_q + (size_t)h * S_TOT * DHEAD;
    const float* Kg = g_k + (size_t)h * S_TOT * DHEAD;
    const float* Vg = g_v + (size_t)h * S_TOT * DHEAD;

    // Load Q tile transposed
#pragma unroll
    for (int t = 0; t < 4; t++) {
        int e = tid + t * 256;              // 0..1023
        int r = e >> 4;                     // 0..63
        int d4 = e & 15;                    // 0..15
        float4 v = *(const float4*)(Qg + (size_t)(q0 + r) * DHEAD + d4 * 4);
        Qt[(d4 * 4 + 0) * SMSTR + r] = v.x;
        Qt[(d4 * 4 + 1) * SMSTR + r] = v.y;
        Qt[(d4 * 4 + 2) * SMSTR + r] = v.z;
        Qt[(d4 * 4 + 3) * SMSTR + r] = v.w;
    }

    float m_i[4], l_i[4], o[4][4];
#pragma unroll
    for (int i = 0; i < 4; i++) {
        m_i[i] = -1e30f;
        l_i[i] = 0.0f;
#pragma unroll
        for (int j = 0; j < 4; j++) o[i][j] = 0.0f;
    }

    for (int kt = 0; kt < S_TOT / 64; kt++) {
        const int c0 = kt * 64;
        // Load K (transposed) and V (natural)
#pragma unroll
        for (int t = 0; t < 4; t++) {
            int e = tid + t * 256;
            int r = e >> 4;
            int d4 = e & 15;
            float4 kv = *(const float4*)(Kg + (size_t)(c0 + r) * DHEAD + d4 * 4);
            Kt[(d4 * 4 + 0) * SMSTR + r] = kv.x;
            Kt[(d4 * 4 + 1) * SMSTR + r] = kv.y;
            Kt[(d4 * 4 + 2) * SMSTR + r] = kv.z;
            Kt[(d4 * 4 + 3) * SMSTR + r] = kv.w;
            float4 vv = *(const float4*)(Vg + (size_t)(c0 + r) * DHEAD + d4 * 4);
            *(float4*)&Vs[r * SMSTR + d4 * 4] = vv;
        }
        __syncthreads();

        // S = Q K^T (scaled)
        float s_[4][4];
#pragma unroll
        for (int i = 0; i < 4; i++)
#pragma unroll
            for (int j = 0; j < 4; j++) s_[i][j] = 0.0f;

#pragma unroll 16
        for (int d = 0; d < 64; d++) {
            float4 a = *(const float4*)&Qt[d * SMSTR + ty * 4];
            float4 b = *(const float4*)&Kt[d * SMSTR + tx * 4];
            float av[4] = {a.x, a.y, a.z, a.w};
            float bv[4] = {b.x, b.y, b.z, b.w};
#pragma unroll
            for (int i = 0; i < 4; i++)
#pragma unroll
                for (int j = 0; j < 4; j++)
                    s_[i][j] = fmaf(av[i], bv[j], s_[i][j]);
        }

        // Online softmax per row (rows of this thread: 4ty..4ty+3)
#pragma unroll
        for (int i = 0; i < 4; i++) {
            float mx = -1e30f;
#pragma unroll
            for (int j = 0; j < 4; j++) {
                s_[i][j] *= 0.125f;           // DH^-0.5
                mx = fmaxf(mx, s_[i][j]);
            }
#pragma unroll
            for (int m = 8; m; m >>= 1)
                mx = fmaxf(mx, __shfl_xor_sync(0xffffffffu, mx, m));
            float mn = fmaxf(m_i[i], mx);
            float f = __expf(m_i[i] - mn);
            float sum = 0.0f;
#pragma unroll
            for (int j = 0; j < 4; j++) {
                float p = __expf(s_[i][j] - mn);
                s_[i][j] = p;
                sum += p;
            }
#pragma unroll
            for (int m = 8; m; m >>= 1)
                sum += __shfl_xor_sync(0xffffffffu, sum, m);
            l_i[i] = l_i[i] * f + sum;
            m_i[i] = mn;
#pragma unroll
            for (int j = 0; j < 4; j++) o[i][j] *= f;
            *(float4*)&Ps[(ty * 4 + i) * SMSTR + tx * 4] =
                make_float4(s_[i][0], s_[i][1], s_[i][2], s_[i][3]);
        }
        __syncthreads();

        // O += P @ V
#pragma unroll 8
        for (int c = 0; c < 64; c++) {
            float4 b = *(const float4*)&Vs[c * SMSTR + tx * 4];
#pragma unroll
            for (int i = 0; i < 4; i++) {
                float a = Ps[(ty * 4 + i) * SMSTR + c];
                o[i][0] = fmaf(a, b.x, o[i][0]);
                o[i][1] = fmaf(a, b.y, o[i][1]);
                o[i][2] = fmaf(a, b.z, o[i][2]);
                o[i][3] = fmaf(a, b.w, o[i][3]);
            }
        }
        __syncthreads();
    }

    // Normalize and write token-major [s][h*64+dv]
#pragma unroll
    for (int i = 0; i < 4; i++) {
        float inv = 1.0f / l_i[i];
        float4 r = make_float4(o[i][0] * inv, o[i][1] * inv,
                               o[i][2] * inv, o[i][3] * inv);
        *(float4*)(g_attn + (size_t)(q0 + ty * 4 + i) * DMODEL + h * DHEAD + tx * 4) = r;
    }
}

// ---------------------------------------------------------------------------
// Launch
// ---------------------------------------------------------------------------
extern "C" void kernel_launch(void* const* d_in, const int* in_sizes, int n_in,
                              void* d_out, int out_size)
{
    (void)in_sizes; (void)n_in; (void)out_size;
    const float* hs  = (const float*)d_in[0];
    const float* enc = (const float*)d_in[1];
    const float* rc  = (const float*)d_in[2];
    const float* rs  = (const float*)d_in[3];
    const float* Wq  = (const float*)d_in[4];  const float* bq  = (const float*)d_in[5];
    const float* Wk  = (const float*)d_in[6];  const float* bk  = (const float*)d_in[7];
    const float* Wv  = (const float*)d_in[8];  const float* bv  = (const float*)d_in[9];
    const float* Waq = (const float*)d_in[10]; const float* baq = (const float*)d_in[11];
    const float* Wak = (const float*)d_in[12]; const float* bak = (const float*)d_in[13];
    const float* Wav = (const float*)d_in[14]; const float* bav = (const float*)d_in[15];
    const float* Wo  = (const float*)d_in[16]; const float* bo  = (const float*)d_in[17];
    const float* Wao = (const float*)d_in[18]; const float* bao = (const float*)d_in[19];
    const float* gq  = (const float*)d_in[20]; const float* gk  = (const float*)d_in[21];
    const float* gaq = (const float*)d_in[22]; const float* gak = (const float*)d_in[23];
    float* out = (float*)d_out;

    void *pq, *pk, *pv, *pa;
    cudaGetSymbolAddress(&pq, g_q);
    cudaGetSymbolAddress(&pk, g_k);
    cudaGetSymbolAddress(&pv, g_v);
    cudaGetSymbolAddress(&pa, g_attn);
    float* fq = (float*)pq;
    float* fk = (float*)pk;
    float* fv = (float*)pv;
    float* fa = (float*)pa;

    const int SMEM_GEMM = 4 * TSZ * (int)sizeof(uint32_t);        // 73728
    const int SMEM_ATTN = 4 * 64 * SMSTR * (int)sizeof(float);    // 69632
    cudaFuncSetAttribute(gemm_tc, cudaFuncAttributeMaxDynamicSharedMemorySize,
                         SMEM_GEMM);
    cudaFuncSetAttribute(attn_kernel, cudaFuncAttributeMaxDynamicSharedMemorySize,
                         SMEM_ATTN);

    dim3 gi3(12, S_IMG / 128, 3);   // batched image QKV
    dim3 gt3(12, S_TXT / 128, 3);   // batched text QKV
    dim3 gi1(12, S_IMG / 128, 1);
    dim3 gt1(12, S_TXT / 128, 1);

    // QKV projections -> head-major with concat offset (text tokens 0..511)
    gemm_tc<<<gi3, 512, SMEM_GEMM>>>(hs, Wq, Wk, Wv, bq, bk, bv,
                                     fq, fk, fv, 1, S_TXT);
    gemm_tc<<<gt3, 512, SMEM_GEMM>>>(enc, Waq, Wak, Wav, baq, bak, bav,
                                     fq, fk, fv, 1, 0);

    // RMS norm + RoPE on q and k
    {
        int warps = 2 * NHEAD * S_TOT;
        int blocks = (warps * 32 + 255) / 256;
        rmsrope_kernel<<<blocks, 256>>>(rc, rs, gq, gk, gaq, gak);
    }

    // Attention
    attn_kernel<<<dim3(S_TOT / 64, NHEAD), 256, SMEM_ATTN>>>();

    // Output projections: img rows 512.., enc rows 0..511
    gemm_tc<<<gi1, 512, SMEM_GEMM>>>(fa + (size_t)S_TXT * DMODEL,
                                     Wo, Wo, Wo, bo, bo, bo,
                                     out, out, out, 0, 0);
    gemm_tc<<<gt1, 512, SMEM_GEMM>>>(fa, Wao, Wao, Wao, bao, bao, bao,
                                     out + (size_t)S_IMG * DMODEL,
                                     out + (size_t)S_IMG * DMODEL,
                                     out + (size_t)S_IMG * DMODEL, 0, 0);
}

// round 8
// speedup vs baseline: 1.0008x; 1.0008x over previous
#include <cuda_runtime.h>
#include <math.h>
#include <stdint.h>

// Problem constants
#define S_IMG 2048
#define S_TXT 512
#define S_TOT 2560
#define DMODEL 1536
#define NHEAD 24
#define DHEAD 64

// Scratch (device globals; no allocation allowed)
__device__ __align__(16) float g_q[NHEAD * S_TOT * DHEAD];
__device__ __align__(16) float g_k[NHEAD * S_TOT * DHEAD];
__device__ __align__(16) float g_v[NHEAD * S_TOT * DHEAD];
__device__ __align__(16) float g_attn[S_TOT * DMODEL];

// ---------------------------------------------------------------------------
// tf32 helpers
// ---------------------------------------------------------------------------
__device__ __forceinline__ uint32_t f2tf(float x) {
    uint32_t u;
    asm("cvt.rna.tf32.f32 %0, %1;" : "=r"(u) : "f"(x));
    return u;
}

#define MMA_TF32(d, a, b)                                                     \
    asm volatile(                                                             \
        "mma.sync.aligned.m16n8k8.row.col.f32.tf32.tf32.f32 "                 \
        "{%0,%1,%2,%3}, {%4,%5,%6,%7}, {%8,%9}, {%0,%1,%2,%3};"               \
        : "+f"((d)[0]), "+f"((d)[1]), "+f"((d)[2]), "+f"((d)[3])              \
        : "r"((a)[0]), "r"((a)[1]), "r"((a)[2]), "r"((a)[3]),                 \
          "r"((b)[0]), "r"((b)[1]))

// ---------------------------------------------------------------------------
// Tensor-core GEMM (tf32): out = A[M,1536] @ W[1536,1536]^T + bias
//   gridDim.z selects (W, bias, out) triple -> batches QKV in one launch.
//   headmajor==1: out[(h*S_TOT + tok_off + m)*64 + d]  (n = h*64+d)
//   headmajor==0: out[m*1536 + n]
// Tiles: BM=BN=128, BK=32. 512 threads = 16 warps (4x4), warp tile 32x32.
// Smem [row][k] padded to stride 36 words -> all fragment LDS conflict-free.
// Double-buffered (global -> regs -> smem). Dynamic smem = 73728 B.
// ---------------------------------------------------------------------------
#define KPAD 36
#define TSZ (128 * KPAD)   // words per (matrix, buffer)

__global__ __launch_bounds__(512, 1)
void gemm_tc(const float* __restrict__ A,
             const float* __restrict__ W0, const float* __restrict__ W1,
             const float* __restrict__ W2,
             const float* __restrict__ bz0, const float* __restrict__ bz1,
             const float* __restrict__ bz2,
             float* __restrict__ o0, float* __restrict__ o1,
             float* __restrict__ o2,
             int headmajor, int tok_off)
{
    extern __shared__ uint32_t smu[];
    uint32_t* As = smu;              // [2][128][36]
    uint32_t* Bs = smu + 2 * TSZ;    // [2][128][36]

    const float* W    = (blockIdx.z == 0) ? W0  : (blockIdx.z == 1 ? W1  : W2);
    const float* bias = (blockIdx.z == 0) ? bz0 : (blockIdx.z == 1 ? bz1 : bz2);
    float* out        = (blockIdx.z == 0) ? o0  : (blockIdx.z == 1 ? o1  : o2);

    const int m0 = blockIdx.y * 128;
    const int n0 = blockIdx.x * 128;
    const int tid = threadIdx.x;
    const int lane = tid & 31;
    const int wid = tid >> 5;
    const int wm = wid >> 2;     // 0..3
    const int wn = wid & 3;      // 0..3
    const int gid = lane >> 2;   // 0..7
    const int tg = lane & 3;     // 0..3

    const float* Ap = A + (size_t)m0 * DMODEL;
    const float* Wp = W + (size_t)n0 * DMODEL;

    // Global-load coords: 2 float4 per matrix per thread.
    // f = tid + i*512; row = f>>3 (0..127); c4 = f&7 (float4 within 32-wide k)
    const int r0 = tid >> 3,          c0 = tid & 7;
    const int r1 = (tid + 512) >> 3,  c1 = (tid + 512) & 7;

    float acc[2][4][4];
#pragma unroll
    for (int mf = 0; mf < 2; mf++)
#pragma unroll
        for (int nf = 0; nf < 4; nf++)
#pragma unroll
            for (int j = 0; j < 4; j++) acc[mf][nf][j] = 0.0f;

    // Prologue: tile k0=0 -> buffer 0
    {
        float4 a0 = *(const float4*)(Ap + (size_t)r0 * DMODEL + c0 * 4);
        float4 a1 = *(const float4*)(Ap + (size_t)r1 * DMODEL + c1 * 4);
        float4 b0 = *(const float4*)(Wp + (size_t)r0 * DMODEL + c0 * 4);
        float4 b1 = *(const float4*)(Wp + (size_t)r1 * DMODEL + c1 * 4);
        uint32_t* d;
        d = As + r0 * KPAD + c0 * 4;
        d[0] = f2tf(a0.x); d[1] = f2tf(a0.y); d[2] = f2tf(a0.z); d[3] = f2tf(a0.w);
        d = As + r1 * KPAD + c1 * 4;
        d[0] = f2tf(a1.x); d[1] = f2tf(a1.y); d[2] = f2tf(a1.z); d[3] = f2tf(a1.w);
        d = Bs + r0 * KPAD + c0 * 4;
        d[0] = f2tf(b0.x); d[1] = f2tf(b0.y); d[2] = f2tf(b0.z); d[3] = f2tf(b0.w);
        d = Bs + r1 * KPAD + c1 * 4;
        d[0] = f2tf(b1.x); d[1] = f2tf(b1.y); d[2] = f2tf(b1.z); d[3] = f2tf(b1.w);
    }
    __syncthreads();

    int buf = 0;
    for (int k0 = 0; k0 < DMODEL; k0 += 32) {
        // Prefetch next tile into registers
        float4 pa0, pa1, pb0, pb1;
        const int kn = k0 + 32;
        if (kn < DMODEL) {
            pa0 = *(const float4*)(Ap + (size_t)r0 * DMODEL + kn + c0 * 4);
            pa1 = *(const float4*)(Ap + (size_t)r1 * DMODEL + kn + c1 * 4);
            pb0 = *(const float4*)(Wp + (size_t)r0 * DMODEL + kn + c0 * 4);
            pb1 = *(const float4*)(Wp + (size_t)r1 * DMODEL + kn + c1 * 4);
        }

        const uint32_t* asb = As + buf * TSZ;
        const uint32_t* bsb = Bs + buf * TSZ;

#pragma unroll
        for (int kk = 0; kk < 4; kk++) {
            const uint32_t* ak = asb + kk * 8;
            const uint32_t* bk = bsb + kk * 8;
            uint32_t a[2][4], b[4][2];
            const int ra = wm * 32 + gid;
            a[0][0] = ak[(ra)      * KPAD + tg];
            a[0][1] = ak[(ra + 8)  * KPAD + tg];
            a[0][2] = ak[(ra)      * KPAD + tg + 4];
            a[0][3] = ak[(ra + 8)  * KPAD + tg + 4];
            a[1][0] = ak[(ra + 16) * KPAD + tg];
            a[1][1] = ak[(ra + 24) * KPAD + tg];
            a[1][2] = ak[(ra + 16) * KPAD + tg + 4];
            a[1][3] = ak[(ra + 24) * KPAD + tg + 4];
#pragma unroll
            for (int nf = 0; nf < 4; nf++) {
                const int cb = wn * 32 + nf * 8 + gid;
                b[nf][0] = bk[cb * KPAD + tg];
                b[nf][1] = bk[cb * KPAD + tg + 4];
            }
#pragma unroll
            for (int mf = 0; mf < 2; mf++)
#pragma unroll
                for (int nf = 0; nf < 4; nf++)
                    MMA_TF32(acc[mf][nf], a[mf], b[nf]);
        }

        if (kn < DMODEL) {
            const int nb = buf ^ 1;
            uint32_t* d;
            d = As + nb * TSZ + r0 * KPAD + c0 * 4;
            d[0] = f2tf(pa0.x); d[1] = f2tf(pa0.y); d[2] = f2tf(pa0.z); d[3] = f2tf(pa0.w);
            d = As + nb * TSZ + r1 * KPAD + c1 * 4;
            d[0] = f2tf(pa1.x); d[1] = f2tf(pa1.y); d[2] = f2tf(pa1.z); d[3] = f2tf(pa1.w);
            d = Bs + nb * TSZ + r0 * KPAD + c0 * 4;
            d[0] = f2tf(pb0.x); d[1] = f2tf(pb0.y); d[2] = f2tf(pb0.z); d[3] = f2tf(pb0.w);
            d = Bs + nb * TSZ + r1 * KPAD + c1 * 4;
            d[0] = f2tf(pb1.x); d[1] = f2tf(pb1.y); d[2] = f2tf(pb1.z); d[3] = f2tf(pb1.w);
            __syncthreads();
            buf = nb;
        }
    }

    // Epilogue: c0/c1 -> row gid, cols tg*2, tg*2+1; c2/c3 -> row gid+8
#pragma unroll
    for (int mf = 0; mf < 2; mf++) {
        const int rowa = m0 + wm * 32 + mf * 16 + gid;
#pragma unroll
        for (int nf = 0; nf < 4; nf++) {
            const int n = n0 + wn * 32 + nf * 8 + tg * 2;
            float2 bb = *(const float2*)(bias + n);
            float2 v0 = make_float2(acc[mf][nf][0] + bb.x, acc[mf][nf][1] + bb.y);
            float2 v1 = make_float2(acc[mf][nf][2] + bb.x, acc[mf][nf][3] + bb.y);
            if (headmajor) {
                const int hh = n >> 6;
                const int dd = n & 63;
                float* p0 = out + ((size_t)(hh * S_TOT + tok_off + rowa)) * DHEAD + dd;
                float* p1 = out + ((size_t)(hh * S_TOT + tok_off + rowa + 8)) * DHEAD + dd;
                *(float2*)p0 = v0;
                *(float2*)p1 = v1;
            } else {
                *(float2*)(out + (size_t)rowa * DMODEL + n) = v0;
                *(float2*)(out + (size_t)(rowa + 8) * DMODEL + n) = v1;
            }
        }
    }
}

// ---------------------------------------------------------------------------
// Fused per-(token, head) RMS norm + RoPE on g_q and g_k (v untouched).
// One warp per 64-element row; lane handles elements (2*lane, 2*lane+1).
// ---------------------------------------------------------------------------
__global__ void rmsrope_kernel(const float* __restrict__ cosb,
                               const float* __restrict__ sinb,
                               const float* __restrict__ gq,
                               const float* __restrict__ gk,
                               const float* __restrict__ gaq,
                               const float* __restrict__ gak)
{
    int wg = (blockIdx.x * blockDim.x + threadIdx.x) >> 5;   // global warp id
    int lane = threadIdx.x & 31;
    const int ROWS = NHEAD * S_TOT;
    if (wg >= 2 * ROWS) return;

    int which = (wg >= ROWS) ? 1 : 0;      // 0 = q, 1 = k
    int r = which ? (wg - ROWS) : wg;      // r = h*S_TOT + s
    int s = r % S_TOT;

    float* ptr = (which ? g_k : g_q) + (size_t)r * DHEAD;
    const float* g = which ? (s < S_TXT ? gak : gk)
                           : (s < S_TXT ? gaq : gq);

    float2 x = ((float2*)ptr)[lane];
    float ss = x.x * x.x + x.y * x.y;
#pragma unroll
    for (int m = 16; m; m >>= 1) ss += __shfl_xor_sync(0xffffffffu, ss, m);
    float sc = rsqrtf(ss * (1.0f / DHEAD) + 1e-6f);

    float x0 = x.x * sc * g[2 * lane];
    float x1 = x.y * sc * g[2 * lane + 1];

    float c  = cosb[s * DHEAD + 2 * lane];   // repeated pairs: [2d] == [2d+1]
    float sn = sinb[s * DHEAD + 2 * lane];

    float2 y;
    y.x = x0 * c - x1 * sn;
    y.y = x1 * c + x0 * sn;
    ((float2*)ptr)[lane] = y;
}

// ---------------------------------------------------------------------------
// FlashAttention fp32. Grid: (S_TOT/64 q-tiles, NHEAD). 256 threads.
// 64x64 S tile; thread (ty,tx) in 16x16 grid owns 4x4 micro-tile.
// Qt/Kt transposed [d][row] with stride 68 (conflict-light); Vs/Ps natural.
// Dynamic smem: 4 * 64*68 * 4B = 69632 B.
// ---------------------------------------------------------------------------
#define SMSTR 68
__global__ __launch_bounds__(256, 2)
void attn_kernel()
{
    extern __shared__ float sm[];
    float* Qt = sm;                 // [64][68]  Qt[d][r]
    float* Kt = sm + 64 * SMSTR;    // [64][68]  Kt[d][c]
    float* Vs = sm + 2 * 64 * SMSTR;// [64][68]  Vs[c][dv]
    float* Ps = sm + 3 * 64 * SMSTR;// [64][68]  Ps[r][c]

    const int h = blockIdx.y;
    const int q0 = blockIdx.x * 64;
    const int tid = threadIdx.x;
    const int tx = tid & 15;
    const int ty = tid >> 4;

    const float* Qg = g_q + (size_t)h * S_TOT * DHEAD;
    const float* Kg = g_k + (size_t)h * S_TOT * DHEAD;
    const float* Vg = g_v + (size_t)h * S_TOT * DHEAD;

    // Load Q tile transposed
#pragma unroll
    for (int t = 0; t < 4; t++) {
        int e = tid + t * 256;              // 0..1023
        int r = e >> 4;                     // 0..63
        int d4 = e & 15;                    // 0..15
        float4 v = *(const float4*)(Qg + (size_t)(q0 + r) * DHEAD + d4 * 4);
        Qt[(d4 * 4 + 0) * SMSTR + r] = v.x;
        Qt[(d4 * 4 + 1) * SMSTR + r] = v.y;
        Qt[(d4 * 4 + 2) * SMSTR + r] = v.z;
        Qt[(d4 * 4 + 3) * SMSTR + r] = v.w;
    }

    float m_i[4], l_i[4], o[4][4];
#pragma unroll
    for (int i = 0; i < 4; i++) {
        m_i[i] = -1e30f;
        l_i[i] = 0.0f;
#pragma unroll
        for (int j = 0; j < 4; j++) o[i][j] = 0.0f;
    }

    for (int kt = 0; kt < S_TOT / 64; kt++) {
        const int c0 = kt * 64;
        // Load K (transposed) and V (natural)
#pragma unroll
        for (int t = 0; t < 4; t++) {
            int e = tid + t * 256;
            int r = e >> 4;
            int d4 = e & 15;
            float4 kv = *(const float4*)(Kg + (size_t)(c0 + r) * DHEAD + d4 * 4);
            Kt[(d4 * 4 + 0) * SMSTR + r] = kv.x;
            Kt[(d4 * 4 + 1) * SMSTR + r] = kv.y;
            Kt[(d4 * 4 + 2) * SMSTR + r] = kv.z;
            Kt[(d4 * 4 + 3) * SMSTR + r] = kv.w;
            float4 vv = *(const float4*)(Vg + (size_t)(c0 + r) * DHEAD + d4 * 4);
            *(float4*)&Vs[r * SMSTR + d4 * 4] = vv;
        }
        __syncthreads();

        // S = Q K^T (scaled)
        float s_[4][4];
#pragma unroll
        for (int i = 0; i < 4; i++)
#pragma unroll
            for (int j = 0; j < 4; j++) s_[i][j] = 0.0f;

#pragma unroll 16
        for (int d = 0; d < 64; d++) {
            float4 a = *(const float4*)&Qt[d * SMSTR + ty * 4];
            float4 b = *(const float4*)&Kt[d * SMSTR + tx * 4];
            float av[4] = {a.x, a.y, a.z, a.w};
            float bv[4] = {b.x, b.y, b.z, b.w};
#pragma unroll
            for (int i = 0; i < 4; i++)
#pragma unroll
                for (int j = 0; j < 4; j++)
                    s_[i][j] = fmaf(av[i], bv[j], s_[i][j]);
        }

        // Online softmax per row (rows of this thread: 4ty..4ty+3)
#pragma unroll
        for (int i = 0; i < 4; i++) {
            float mx = -1e30f;
#pragma unroll
            for (int j = 0; j < 4; j++) {
                s_[i][j] *= 0.125f;           // DH^-0.5
                mx = fmaxf(mx, s_[i][j]);
            }
#pragma unroll
            for (int m = 8; m; m >>= 1)
                mx = fmaxf(mx, __shfl_xor_sync(0xffffffffu, mx, m));
            float mn = fmaxf(m_i[i], mx);
            float f = __expf(m_i[i] - mn);
            float sum = 0.0f;
#pragma unroll
            for (int j = 0; j < 4; j++) {
                float p = __expf(s_[i][j] - mn);
                s_[i][j] = p;
                sum += p;
            }
#pragma unroll
            for (int m = 8; m; m >>= 1)
                sum += __shfl_xor_sync(0xffffffffu, sum, m);
            l_i[i] = l_i[i] * f + sum;
            m_i[i] = mn;
#pragma unroll
            for (int j = 0; j < 4; j++) o[i][j] *= f;
            *(float4*)&Ps[(ty * 4 + i) * SMSTR + tx * 4] =
                make_float4(s_[i][0], s_[i][1], s_[i][2], s_[i][3]);
        }
        __syncthreads();

        // O += P @ V
#pragma unroll 8
        for (int c = 0; c < 64; c++) {
            float4 b = *(const float4*)&Vs[c * SMSTR + tx * 4];
#pragma unroll
            for (int i = 0; i < 4; i++) {
                float a = Ps[(ty * 4 + i) * SMSTR + c];
                o[i][0] = fmaf(a, b.x, o[i][0]);
                o[i][1] = fmaf(a, b.y, o[i][1]);
                o[i][2] = fmaf(a, b.z, o[i][2]);
                o[i][3] = fmaf(a, b.w, o[i][3]);
            }
        }
        __syncthreads();
    }

    // Normalize and write token-major [s][h*64+dv]
#pragma unroll
    for (int i = 0; i < 4; i++) {
        float inv = 1.0f / l_i[i];
        float4 r = make_float4(o[i][0] * inv, o[i][1] * inv,
                               o[i][2] * inv, o[i][3] * inv);
        *(float4*)(g_attn + (size_t)(q0 + ty * 4 + i) * DMODEL + h * DHEAD + tx * 4) = r;
    }
}

// ---------------------------------------------------------------------------
// Launch
// ---------------------------------------------------------------------------
extern "C" void kernel_launch(void* const* d_in, const int* in_sizes, int n_in,
                              void* d_out, int out_size)
{
    (void)in_sizes; (void)n_in; (void)out_size;
    const float* hs  = (const float*)d_in[0];
    const float* enc = (const float*)d_in[1];
    const float* rc  = (const float*)d_in[2];
    const float* rs  = (const float*)d_in[3];
    const float* Wq  = (const float*)d_in[4];  const float* bq  = (const float*)d_in[5];
    const float* Wk  = (const float*)d_in[6];  const float* bk  = (const float*)d_in[7];
    const float* Wv  = (const float*)d_in[8];  const float* bv  = (const float*)d_in[9];
    const float* Waq = (const float*)d_in[10]; const float* baq = (const float*)d_in[11];
    const float* Wak = (const float*)d_in[12]; const float* bak = (const float*)d_in[13];
    const float* Wav = (const float*)d_in[14]; const float* bav = (const float*)d_in[15];
    const float* Wo  = (const float*)d_in[16]; const float* bo  = (const float*)d_in[17];
    const float* Wao = (const float*)d_in[18]; const float* bao = (const float*)d_in[19];
    const float* gq  = (const float*)d_in[20]; const float* gk  = (const float*)d_in[21];
    const float* gaq = (const float*)d_in[22]; const float* gak = (const float*)d_in[23];
    float* out = (float*)d_out;

    void *pq, *pk, *pv, *pa;
    cudaGetSymbolAddress(&pq, g_q);
    cudaGetSymbolAddress(&pk, g_k);
    cudaGetSymbolAddress(&pv, g_v);
    cudaGetSymbolAddress(&pa, g_attn);
    float* fq = (float*)pq;
    float* fk = (float*)pk;
    float* fv = (float*)pv;
    float* fa = (float*)pa;

    const int SMEM_GEMM = 4 * TSZ * (int)sizeof(uint32_t);        // 73728
    const int SMEM_ATTN = 4 * 64 * SMSTR * (int)sizeof(float);    // 69632
    cudaFuncSetAttribute(gemm_tc, cudaFuncAttributeMaxDynamicSharedMemorySize,
                         SMEM_GEMM);
    cudaFuncSetAttribute(attn_kernel, cudaFuncAttributeMaxDynamicSharedMemorySize,
                         SMEM_ATTN);

    dim3 gi3(12, S_IMG / 128, 3);   // batched image QKV
    dim3 gt3(12, S_TXT / 128, 3);   // batched text QKV
    dim3 gi1(12, S_IMG / 128, 1);
    dim3 gt1(12, S_TXT / 128, 1);

    // QKV projections -> head-major with concat offset (text tokens 0..511)
    gemm_tc<<<gi3, 512, SMEM_GEMM>>>(hs, Wq, Wk, Wv, bq, bk, bv,
                                     fq, fk, fv, 1, S_TXT);
    gemm_tc<<<gt3, 512, SMEM_GEMM>>>(enc, Waq, Wak, Wav, baq, bak, bav,
                                     fq, fk, fv, 1, 0);

    // RMS norm + RoPE on q and k
    {
        int warps = 2 * NHEAD * S_TOT;
        int blocks = (warps * 32 + 255) / 256;
        rmsrope_kernel<<<blocks, 256>>>(rc, rs, gq, gk, gaq, gak);
    }

    // Attention
    attn_kernel<<<dim3(S_TOT / 64, NHEAD), 256, SMEM_ATTN>>>();

    // Output projections: img rows 512.., enc rows 0..511
    gemm_tc<<<gi1, 512, SMEM_GEMM>>>(fa + (size_t)S_TXT * DMODEL,
                                     Wo, Wo, Wo, bo, bo, bo,
                                     out, out, out, 0, 0);
    gemm_tc<<<gt1, 512, SMEM_GEMM>>>(fa, Wao, Wao, Wao, bao, bao, bao,
                                     out + (size_t)S_IMG * DMODEL,
                                     out + (size_t)S_IMG * DMODEL,
                                     out + (size_t)S_IMG * DMODEL, 0, 0);
}

// round 9
// speedup vs baseline: 1.0016x; 1.0008x over previous
#include <cuda_runtime.h>
#include <math.h>
#include <stdint.h>

// Problem constants
#define S_IMG 2048
#define S_TXT 512
#define S_TOT 2560
#define DMODEL 1536
#define NHEAD 24
#define DHEAD 64

// Scratch (device globals; no allocation allowed)
__device__ __align__(16) float g_q[NHEAD * S_TOT * DHEAD];
__device__ __align__(16) float g_k[NHEAD * S_TOT * DHEAD];
__device__ __align__(16) float g_v[NHEAD * S_TOT * DHEAD];
__device__ __align__(16) float g_attn[S_TOT * DMODEL];

// ---------------------------------------------------------------------------
// tf32 helpers
// ---------------------------------------------------------------------------
__device__ __forceinline__ uint32_t f2tf(float x) {
    uint32_t u;
    asm("cvt.rna.tf32.f32 %0, %1;" : "=r"(u) : "f"(x));
    return u;
}

#define MMA_TF32(d, a, b)                                                     \
    asm volatile(                                                             \
        "mma.sync.aligned.m16n8k8.row.col.f32.tf32.tf32.f32 "                 \
        "{%0,%1,%2,%3}, {%4,%5,%6,%7}, {%8,%9}, {%0,%1,%2,%3};"               \
        : "+f"((d)[0]), "+f"((d)[1]), "+f"((d)[2]), "+f"((d)[3])              \
        : "r"((a)[0]), "r"((a)[1]), "r"((a)[2]), "r"((a)[3]),                 \
          "r"((b)[0]), "r"((b)[1]))

// ---------------------------------------------------------------------------
// Tensor-core GEMM (tf32): out = A[M,1536] @ W[1536,1536]^T + bias
//   gridDim.z selects (W, bias, out) triple -> batches QKV in one launch.
//   headmajor==1: out[(h*S_TOT + tok_off + m)*64 + d]  (n = h*64+d)
//   headmajor==0: out[m*1536 + n]
// Tiles: BM=BN=128, BK=32. 512 threads = 16 warps (4x4), warp tile 32x32.
// Smem [row][k] padded to stride 36 words -> all fragment LDS conflict-free.
// Double-buffered (global -> regs -> smem). Dynamic smem = 73728 B.
// ---------------------------------------------------------------------------
#define KPAD 36
#define TSZ (128 * KPAD)   // words per (matrix, buffer)

__global__ __launch_bounds__(512, 1)
void gemm_tc(const float* __restrict__ A,
             const float* __restrict__ W0, const float* __restrict__ W1,
             const float* __restrict__ W2,
             const float* __restrict__ bz0, const float* __restrict__ bz1,
             const float* __restrict__ bz2,
             float* __restrict__ o0, float* __restrict__ o1,
             float* __restrict__ o2,
             int headmajor, int tok_off)
{
    extern __shared__ uint32_t smu[];
    uint32_t* As = smu;              // [2][128][36]
    uint32_t* Bs = smu + 2 * TSZ;    // [2][128][36]

    const float* W    = (blockIdx.z == 0) ? W0  : (blockIdx.z == 1 ? W1  : W2);
    const float* bias = (blockIdx.z == 0) ? bz0 : (blockIdx.z == 1 ? bz1 : bz2);
    float* out        = (blockIdx.z == 0) ? o0  : (blockIdx.z == 1 ? o1  : o2);

    const int m0 = blockIdx.y * 128;
    const int n0 = blockIdx.x * 128;
    const int tid = threadIdx.x;
    const int lane = tid & 31;
    const int wid = tid >> 5;
    const int wm = wid >> 2;     // 0..3
    const int wn = wid & 3;      // 0..3
    const int gid = lane >> 2;   // 0..7
    const int tg = lane & 3;     // 0..3

    const float* Ap = A + (size_t)m0 * DMODEL;
    const float* Wp = W + (size_t)n0 * DMODEL;

    // Global-load coords: 2 float4 per matrix per thread.
    // f = tid + i*512; row = f>>3 (0..127); c4 = f&7 (float4 within 32-wide k)
    const int r0 = tid >> 3,          c0 = tid & 7;
    const int r1 = (tid + 512) >> 3,  c1 = (tid + 512) & 7;

    float acc[2][4][4];
#pragma unroll
    for (int mf = 0; mf < 2; mf++)
#pragma unroll
        for (int nf = 0; nf < 4; nf++)
#pragma unroll
            for (int j = 0; j < 4; j++) acc[mf][nf][j] = 0.0f;

    // Prologue: tile k0=0 -> buffer 0
    {
        float4 a0 = *(const float4*)(Ap + (size_t)r0 * DMODEL + c0 * 4);
        float4 a1 = *(const float4*)(Ap + (size_t)r1 * DMODEL + c1 * 4);
        float4 b0 = *(const float4*)(Wp + (size_t)r0 * DMODEL + c0 * 4);
        float4 b1 = *(const float4*)(Wp + (size_t)r1 * DMODEL + c1 * 4);
        uint32_t* d;
        d = As + r0 * KPAD + c0 * 4;
        d[0] = f2tf(a0.x); d[1] = f2tf(a0.y); d[2] = f2tf(a0.z); d[3] = f2tf(a0.w);
        d = As + r1 * KPAD + c1 * 4;
        d[0] = f2tf(a1.x); d[1] = f2tf(a1.y); d[2] = f2tf(a1.z); d[3] = f2tf(a1.w);
        d = Bs + r0 * KPAD + c0 * 4;
        d[0] = f2tf(b0.x); d[1] = f2tf(b0.y); d[2] = f2tf(b0.z); d[3] = f2tf(b0.w);
        d = Bs + r1 * KPAD + c1 * 4;
        d[0] = f2tf(b1.x); d[1] = f2tf(b1.y); d[2] = f2tf(b1.z); d[3] = f2tf(b1.w);
    }
    __syncthreads();

    int buf = 0;
    for (int k0 = 0; k0 < DMODEL; k0 += 32) {
        // Prefetch next tile into registers
        float4 pa0, pa1, pb0, pb1;
        const int kn = k0 + 32;
        if (kn < DMODEL) {
            pa0 = *(const float4*)(Ap + (size_t)r0 * DMODEL + kn + c0 * 4);
            pa1 = *(const float4*)(Ap + (size_t)r1 * DMODEL + kn + c1 * 4);
            pb0 = *(const float4*)(Wp + (size_t)r0 * DMODEL + kn + c0 * 4);
            pb1 = *(const float4*)(Wp + (size_t)r1 * DMODEL + kn + c1 * 4);
        }

        const uint32_t* asb = As + buf * TSZ;
        const uint32_t* bsb = Bs + buf * TSZ;

#pragma unroll
        for (int kk = 0; kk < 4; kk++) {
            const uint32_t* ak = asb + kk * 8;
            const uint32_t* bk = bsb + kk * 8;
            uint32_t a[2][4], b[4][2];
            const int ra = wm * 32 + gid;
            a[0][0] = ak[(ra)      * KPAD + tg];
            a[0][1] = ak[(ra + 8)  * KPAD + tg];
            a[0][2] = ak[(ra)      * KPAD + tg + 4];
            a[0][3] = ak[(ra + 8)  * KPAD + tg + 4];
            a[1][0] = ak[(ra + 16) * KPAD + tg];
            a[1][1] = ak[(ra + 24) * KPAD + tg];
            a[1][2] = ak[(ra + 16) * KPAD + tg + 4];
            a[1][3] = ak[(ra + 24) * KPAD + tg + 4];
#pragma unroll
            for (int nf = 0; nf < 4; nf++) {
                const int cb = wn * 32 + nf * 8 + gid;
                b[nf][0] = bk[cb * KPAD + tg];
                b[nf][1] = bk[cb * KPAD + tg + 4];
            }
#pragma unroll
            for (int mf = 0; mf < 2; mf++)
#pragma unroll
                for (int nf = 0; nf < 4; nf++)
                    MMA_TF32(acc[mf][nf], a[mf], b[nf]);
        }

        if (kn < DMODEL) {
            const int nb = buf ^ 1;
            uint32_t* d;
            d = As + nb * TSZ + r0 * KPAD + c0 * 4;
            d[0] = f2tf(pa0.x); d[1] = f2tf(pa0.y); d[2] = f2tf(pa0.z); d[3] = f2tf(pa0.w);
            d = As + nb * TSZ + r1 * KPAD + c1 * 4;
            d[0] = f2tf(pa1.x); d[1] = f2tf(pa1.y); d[2] = f2tf(pa1.z); d[3] = f2tf(pa1.w);
            d = Bs + nb * TSZ + r0 * KPAD + c0 * 4;
            d[0] = f2tf(pb0.x); d[1] = f2tf(pb0.y); d[2] = f2tf(pb0.z); d[3] = f2tf(pb0.w);
            d = Bs + nb * TSZ + r1 * KPAD + c1 * 4;
            d[0] = f2tf(pb1.x); d[1] = f2tf(pb1.y); d[2] = f2tf(pb1.z); d[3] = f2tf(pb1.w);
            __syncthreads();
            buf = nb;
        }
    }

    // Epilogue: c0/c1 -> row gid, cols tg*2, tg*2+1; c2/c3 -> row gid+8
#pragma unroll
    for (int mf = 0; mf < 2; mf++) {
        const int rowa = m0 + wm * 32 + mf * 16 + gid;
#pragma unroll
        for (int nf = 0; nf < 4; nf++) {
            const int n = n0 + wn * 32 + nf * 8 + tg * 2;
            float2 bb = *(const float2*)(bias + n);
            float2 v0 = make_float2(acc[mf][nf][0] + bb.x, acc[mf][nf][1] + bb.y);
            float2 v1 = make_float2(acc[mf][nf][2] + bb.x, acc[mf][nf][3] + bb.y);
            if (headmajor) {
                const int hh = n >> 6;
                const int dd = n & 63;
                float* p0 = out + ((size_t)(hh * S_TOT + tok_off + rowa)) * DHEAD + dd;
                float* p1 = out + ((size_t)(hh * S_TOT + tok_off + rowa + 8)) * DHEAD + dd;
                *(float2*)p0 = v0;
                *(float2*)p1 = v1;
            } else {
                *(float2*)(out + (size_t)rowa * DMODEL + n) = v0;
                *(float2*)(out + (size_t)(rowa + 8) * DMODEL + n) = v1;
            }
        }
    }
}

// ---------------------------------------------------------------------------
// Fused per-(token, head) RMS norm + RoPE on g_q and g_k (v untouched).
// One warp per 64-element row; lane handles elements (2*lane, 2*lane+1).
// ---------------------------------------------------------------------------
__global__ void rmsrope_kernel(const float* __restrict__ cosb,
                               const float* __restrict__ sinb,
                               const float* __restrict__ gq,
                               const float* __restrict__ gk,
                               const float* __restrict__ gaq,
                               const float* __restrict__ gak)
{
    int wg = (blockIdx.x * blockDim.x + threadIdx.x) >> 5;   // global warp id
    int lane = threadIdx.x & 31;
    const int ROWS = NHEAD * S_TOT;
    if (wg >= 2 * ROWS) return;

    int which = (wg >= ROWS) ? 1 : 0;      // 0 = q, 1 = k
    int r = which ? (wg - ROWS) : wg;      // r = h*S_TOT + s
    int s = r % S_TOT;

    float* ptr = (which ? g_k : g_q) + (size_t)r * DHEAD;
    const float* g = which ? (s < S_TXT ? gak : gk)
                           : (s < S_TXT ? gaq : gq);

    float2 x = ((float2*)ptr)[lane];
    float ss = x.x * x.x + x.y * x.y;
#pragma unroll
    for (int m = 16; m; m >>= 1) ss += __shfl_xor_sync(0xffffffffu, ss, m);
    float sc = rsqrtf(ss * (1.0f / DHEAD) + 1e-6f);

    float x0 = x.x * sc * g[2 * lane];
    float x1 = x.y * sc * g[2 * lane + 1];

    float c  = cosb[s * DHEAD + 2 * lane];   // repeated pairs: [2d] == [2d+1]
    float sn = sinb[s * DHEAD + 2 * lane];

    float2 y;
    y.x = x0 * c - x1 * sn;
    y.y = x1 * c + x0 * sn;
    ((float2*)ptr)[lane] = y;
}

// ---------------------------------------------------------------------------
// FlashAttention fp32. Grid: (S_TOT/64 q-tiles, NHEAD). 256 threads.
// 64x64 S tile; thread (ty,tx) in 16x16 grid owns 4x4 micro-tile.
// Qt/Kt transposed [d][row] with stride 68 (conflict-light); Vs/Ps natural.
// Dynamic smem: 4 * 64*68 * 4B = 69632 B.
// ---------------------------------------------------------------------------
#define SMSTR 68
__global__ __launch_bounds__(256, 2)
void attn_kernel()
{
    extern __shared__ float sm[];
    float* Qt = sm;                 // [64][68]  Qt[d][r]
    float* Kt = sm + 64 * SMSTR;    // [64][68]  Kt[d][c]
    float* Vs = sm + 2 * 64 * SMSTR;// [64][68]  Vs[c][dv]
    float* Ps = sm + 3 * 64 * SMSTR;// [64][68]  Ps[r][c]

    const int h = blockIdx.y;
    const int q0 = blockIdx.x * 64;
    const int tid = threadIdx.x;
    const int tx = tid & 15;
    const int ty = tid >> 4;

    const float* Qg = g_q + (size_t)h * S_TOT * DHEAD;
    const float* Kg = g_k + (size_t)h * S_TOT * DHEAD;
    const float* Vg = g_v + (size_t)h * S_TOT * DHEAD;

    // Load Q tile transposed
#pragma unroll
    for (int t = 0; t < 4; t++) {
        int e = tid + t * 256;              // 0..1023
        int r = e >> 4;                     // 0..63
        int d4 = e & 15;                    // 0..15
        float4 v = *(const float4*)(Qg + (size_t)(q0 + r) * DHEAD + d4 * 4);
        Qt[(d4 * 4 + 0) * SMSTR + r] = v.x;
        Qt[(d4 * 4 + 1) * SMSTR + r] = v.y;
        Qt[(d4 * 4 + 2) * SMSTR + r] = v.z;
        Qt[(d4 * 4 + 3) * SMSTR + r] = v.w;
    }

    float m_i[4], l_i[4], o[4][4];
#pragma unroll
    for (int i = 0; i < 4; i++) {
        m_i[i] = -1e30f;
        l_i[i] = 0.0f;
#pragma unroll
        for (int j = 0; j < 4; j++) o[i][j] = 0.0f;
    }

    for (int kt = 0; kt < S_TOT / 64; kt++) {
        const int c0 = kt * 64;
        // Load K (transposed) and V (natural)
#pragma unroll
        for (int t = 0; t < 4; t++) {
            int e = tid + t * 256;
            int r = e >> 4;
            int d4 = e & 15;
            float4 kv = *(const float4*)(Kg + (size_t)(c0 + r) * DHEAD + d4 * 4);
            Kt[(d4 * 4 + 0) * SMSTR + r] = kv.x;
            Kt[(d4 * 4 + 1) * SMSTR + r] = kv.y;
            Kt[(d4 * 4 + 2) * SMSTR + r] = kv.z;
            Kt[(d4 * 4 + 3) * SMSTR + r] = kv.w;
            float4 vv = *(const float4*)(Vg + (size_t)(c0 + r) * DHEAD + d4 * 4);
            *(float4*)&Vs[r * SMSTR + d4 * 4] = vv;
        }
        __syncthreads();

        // S = Q K^T (scaled)
        float s_[4][4];
#pragma unroll
        for (int i = 0; i < 4; i++)
#pragma unroll
            for (int j = 0; j < 4; j++) s_[i][j] = 0.0f;

#pragma unroll 16
        for (int d = 0; d < 64; d++) {
            float4 a = *(const float4*)&Qt[d * SMSTR + ty * 4];
            float4 b = *(const float4*)&Kt[d * SMSTR + tx * 4];
            float av[4] = {a.x, a.y, a.z, a.w};
            float bv[4] = {b.x, b.y, b.z, b.w};
#pragma unroll
            for (int i = 0; i < 4; i++)
#pragma unroll
                for (int j = 0; j < 4; j++)
                    s_[i][j] = fmaf(av[i], bv[j], s_[i][j]);
        }

        // Online softmax per row (rows of this thread: 4ty..4ty+3)
#pragma unroll
        for (int i = 0; i < 4; i++) {
            float mx = -1e30f;
#pragma unroll
            for (int j = 0; j < 4; j++) {
                s_[i][j] *= 0.125f;           // DH^-0.5
                mx = fmaxf(mx, s_[i][j]);
            }
#pragma unroll
            for (int m = 8; m; m >>= 1)
                mx = fmaxf(mx, __shfl_xor_sync(0xffffffffu, mx, m));
            float mn = fmaxf(m_i[i], mx);
            float f = __expf(m_i[i] - mn);
            float sum = 0.0f;
#pragma unroll
            for (int j = 0; j < 4; j++) {
                float p = __expf(s_[i][j] - mn);
                s_[i][j] = p;
                sum += p;
            }
#pragma unroll
            for (int m = 8; m; m >>= 1)
                sum += __shfl_xor_sync(0xffffffffu, sum, m);
            l_i[i] = l_i[i] * f + sum;
            m_i[i] = mn;
#pragma unroll
            for (int j = 0; j < 4; j++) o[i][j] *= f;
            *(float4*)&Ps[(ty * 4 + i) * SMSTR + tx * 4] =
                make_float4(s_[i][0], s_[i][1], s_[i][2], s_[i][3]);
        }
        __syncthreads();

        // O += P @ V
#pragma unroll 8
        for (int c = 0; c < 64; c++) {
            float4 b = *(const float4*)&Vs[c * SMSTR + tx * 4];
#pragma unroll
            for (int i = 0; i < 4; i++) {
                float a = Ps[(ty * 4 + i) * SMSTR + c];
                o[i][0] = fmaf(a, b.x, o[i][0]);
                o[i][1] = fmaf(a, b.y, o[i][1]);
                o[i][2] = fmaf(a, b.z, o[i][2]);
                o[i][3] = fmaf(a, b.w, o[i][3]);
            }
        }
        __syncthreads();
    }

    // Normalize and write token-major [s][h*64+dv]
#pragma unroll
    for (int i = 0; i < 4; i++) {
        float inv = 1.0f / l_i[i];
        float4 r = make_float4(o[i][0] * inv, o[i][1] * inv,
                               o[i][2] * inv, o[i][3] * inv);
        *(float4*)(g_attn + (size_t)(q0 + ty * 4 + i) * DMODEL + h * DHEAD + tx * 4) = r;
    }
}

// ---------------------------------------------------------------------------
// Launch
// ---------------------------------------------------------------------------
extern "C" void kernel_launch(void* const* d_in, const int* in_sizes, int n_in,
                              void* d_out, int out_size)
{
    (void)in_sizes; (void)n_in; (void)out_size;
    const float* hs  = (const float*)d_in[0];
    const float* enc = (const float*)d_in[1];
    const float* rc  = (const float*)d_in[2];
    const float* rs  = (const float*)d_in[3];
    const float* Wq  = (const float*)d_in[4];  const float* bq  = (const float*)d_in[5];
    const float* Wk  = (const float*)d_in[6];  const float* bk  = (const float*)d_in[7];
    const float* Wv  = (const float*)d_in[8];  const float* bv  = (const float*)d_in[9];
    const float* Waq = (const float*)d_in[10]; const float* baq = (const float*)d_in[11];
    const float* Wak = (const float*)d_in[12]; const float* bak = (const float*)d_in[13];
    const float* Wav = (const float*)d_in[14]; const float* bav = (const float*)d_in[15];
    const float* Wo  = (const float*)d_in[16]; const float* bo  = (const float*)d_in[17];
    const float* Wao = (const float*)d_in[18]; const float* bao = (const float*)d_in[19];
    const float* gq  = (const float*)d_in[20]; const float* gk  = (const float*)d_in[21];
    const float* gaq = (const float*)d_in[22]; const float* gak = (const float*)d_in[23];
    float* out = (float*)d_out;

    void *pq, *pk, *pv, *pa;
    cudaGetSymbolAddress(&pq, g_q);
    cudaGetSymbolAddress(&pk, g_k);
    cudaGetSymbolAddress(&pv, g_v);
    cudaGetSymbolAddress(&pa, g_attn);
    float* fq = (float*)pq;
    float* fk = (float*)pk;
    float* fv = (float*)pv;
    float* fa = (float*)pa;

    const int SMEM_GEMM = 4 * TSZ * (int)sizeof(uint32_t);        // 73728
    const int SMEM_ATTN = 4 * 64 * SMSTR * (int)sizeof(float);    // 69632
    cudaFuncSetAttribute(gemm_tc, cudaFuncAttributeMaxDynamicSharedMemorySize,
                         SMEM_GEMM);
    cudaFuncSetAttribute(attn_kernel, cudaFuncAttributeMaxDynamicSharedMemorySize,
                         SMEM_ATTN);

    dim3 gi3(12, S_IMG / 128, 3);   // batched image QKV
    dim3 gt3(12, S_TXT / 128, 3);   // batched text QKV
    dim3 gi1(12, S_IMG / 128, 1);
    dim3 gt1(12, S_TXT / 128, 1);

    // QKV projections -> head-major with concat offset (text tokens 0..511)
    gemm_tc<<<gi3, 512, SMEM_GEMM>>>(hs, Wq, Wk, Wv, bq, bk, bv,
                                     fq, fk, fv, 1, S_TXT);
    gemm_tc<<<gt3, 512, SMEM_GEMM>>>(enc, Waq, Wak, Wav, baq, bak, bav,
                                     fq, fk, fv, 1, 0);

    // RMS norm + RoPE on q and k
    {
        int warps = 2 * NHEAD * S_TOT;
        int blocks = (warps * 32 + 255) / 256;
        rmsrope_kernel<<<blocks, 256>>>(rc, rs, gq, gk, gaq, gak);
    }

    // Attention
    attn_kernel<<<dim3(S_TOT / 64, NHEAD), 256, SMEM_ATTN>>>();

    // Output projections: img rows 512.., enc rows 0..511
    gemm_tc<<<gi1, 512, SMEM_GEMM>>>(fa + (size_t)S_TXT * DMODEL,
                                     Wo, Wo, Wo, bo, bo, bo,
                                     out, out, out, 0, 0);
    gemm_tc<<<gt1, 512, SMEM_GEMM>>>(fa, Wao, Wao, Wao, bao, bao, bao,
                                     out + (size_t)S_IMG * DMODEL,
                                     out + (size_t)S_IMG * DMODEL,
                                     out + (size_t)S_IMG * DMODEL, 0, 0);
}